// round 2
// baseline (speedup 1.0000x reference)
#include <cuda_runtime.h>
#include <cstdint>

// Problem constants
#define N_IMG   16
#define C_IN    64
#define C_OUT   64
#define HH      128
#define WW      128
#define KK      3
#define W_ELEMS (C_OUT * C_IN * KK * KK)   // 36864

// Persistent scratch (no allocations allowed)
__device__ float g_scale[2];                 // scale for w, w_child
__device__ float g_weff[W_ELEMS];            // fused effective weights, layout [c][o][k]
__device__ float g_beff[C_OUT];              // fused bias

// ---------------------------------------------------------------------------
// packed f32x2 helpers (sm_103a FFMA2 path)
// ---------------------------------------------------------------------------
__device__ __forceinline__ unsigned long long pack2(float lo, float hi) {
    unsigned long long r;
    unsigned int a = __float_as_uint(lo), b = __float_as_uint(hi);
    asm("mov.b64 %0, {%1, %2};" : "=l"(r) : "r"(a), "r"(b));
    return r;
}
__device__ __forceinline__ void unpack2(unsigned long long v, float& lo, float& hi) {
    unsigned int a, b;
    asm("mov.b64 {%0, %1}, %2;" : "=r"(a), "=r"(b) : "l"(v));
    lo = __uint_as_float(a);
    hi = __uint_as_float(b);
}
__device__ __forceinline__ unsigned long long ffma2(unsigned long long a,
                                                    unsigned long long b,
                                                    unsigned long long c) {
    unsigned long long d;
    asm("fma.rn.f32x2 %0, %1, %2, %3;" : "=l"(d) : "l"(a), "l"(b), "l"(c));
    return d;
}

// ---------------------------------------------------------------------------
// Kernel 1: per-tensor scale = max(mean(|w|), 1e-5), fp64 accumulation
// ---------------------------------------------------------------------------
__global__ void scale_kernel(const float* __restrict__ w,
                             const float* __restrict__ wc) {
    const float* p = (blockIdx.x == 0) ? w : wc;
    __shared__ double red[256];
    double s = 0.0;
    for (int i = threadIdx.x; i < W_ELEMS; i += 256)
        s += (double)fabsf(p[i]);
    red[threadIdx.x] = s;
    __syncthreads();
    for (int off = 128; off > 0; off >>= 1) {
        if (threadIdx.x < off) red[threadIdx.x] += red[threadIdx.x + off];
        __syncthreads();
    }
    if (threadIdx.x == 0)
        g_scale[blockIdx.x] = fmaxf((float)(red[0] / (double)W_ELEMS), 1e-5f);
}

// ---------------------------------------------------------------------------
// Kernel 2: fuse weights: Weff = Q(w) + sigmoid(gate)*Q(w_child)
// input layout [o][c][kh][kw] -> scratch layout [c][o][k]  (k = kh*3+kw)
// ---------------------------------------------------------------------------
__global__ void prep_kernel(const float* __restrict__ w,
                            const float* __restrict__ b,
                            const float* __restrict__ wc,
                            const float* __restrict__ bc,
                            const float* __restrict__ gate) {
    int i = blockIdx.x * 256 + threadIdx.x;
    float g = 1.0f / (1.0f + expf(-gate[0]));
    if (i < W_ELEMS) {
        float s1 = g_scale[0], s2 = g_scale[1];
        // rintf == round-half-to-even == jnp.round
        float q1 = fminf(fmaxf(rintf(w[i]  / s1), -1.0f), 1.0f) * s1;
        float q2 = fminf(fmaxf(rintf(wc[i] / s2), -1.0f), 1.0f) * s2;
        int o = i / (C_IN * 9);
        int r = i - o * (C_IN * 9);
        int c = r / 9;
        int k = r - c * 9;
        g_weff[c * (C_OUT * 9) + o * 9 + k] = q1 + g * q2;
    }
    if (i < C_OUT)
        g_beff[i] = b[i] + g * bc[i];
}

// ---------------------------------------------------------------------------
// Kernel 3: direct 3x3 conv, pad 1.
// Grid: x = oc-group (4, fastest -> L2 x-tile reuse), y = spatial tile (16),
//       z = image (16).  Block: 256 threads.
// Each block: 32x32 output pixels x 16 output channels.
// Each thread: 2x2 pixel micro-tile x 16 oc, packed-f32x2 accumulators.
// ---------------------------------------------------------------------------
#define XS_STRIDE 35   // 34 cols + pad (odd stride)

__global__ __launch_bounds__(256, 2)
void conv_kernel(const float* __restrict__ x, float* __restrict__ out) {
    const int og = blockIdx.x;            // 0..3   (16 oc each)
    const int sp = blockIdx.y;            // 0..15  spatial tile
    const int n  = blockIdx.z;            // 0..15
    const int sx = sp & 3, sy = sp >> 2;

    const int tid = threadIdx.x;
    const int tx = tid & 15;              // 0..15 -> 2*tx pixel col
    const int ty = tid >> 4;              // 0..15 -> 2*ty pixel row

    __shared__ float xs[34 * XS_STRIDE];
    __shared__ float wsm[16 * 9];

    unsigned long long acc[16][2];
#pragma unroll
    for (int ol = 0; ol < 16; ++ol) { acc[ol][0] = 0ull; acc[ol][1] = 0ull; }

    const float* xn = x + (size_t)n * C_IN * HH * WW;
    const int gx0 = sx * 32 - 1;
    const int gy0 = sy * 32 - 1;

    for (int c = 0; c < C_IN; ++c) {
        const float* xc = xn + (size_t)c * (HH * WW);
        // stage 34x34 input patch (zero-padded at borders)
        for (int i = tid; i < 34 * 34; i += 256) {
            int r = i / 34;
            int col = i - r * 34;
            int gy = gy0 + r, gx = gx0 + col;
            float v = 0.0f;
            if ((unsigned)gy < (unsigned)HH && (unsigned)gx < (unsigned)WW)
                v = xc[gy * WW + gx];
            xs[r * XS_STRIDE + col] = v;
        }
        // stage 16 oc x 9 weights for this input channel
        if (tid < 144)
            wsm[tid] = g_weff[c * (C_OUT * 9) + og * 144 + tid];
        __syncthreads();

        // 4x4 input registers cover all 9 taps of the 2x2 micro-tile
        float xr[4][4];
#pragma unroll
        for (int i = 0; i < 4; ++i)
#pragma unroll
            for (int j = 0; j < 4; ++j)
                xr[i][j] = xs[(2 * ty + i) * XS_STRIDE + 2 * tx + j];

#pragma unroll
        for (int kh = 0; kh < 3; ++kh) {
#pragma unroll
            for (int kw = 0; kw < 3; ++kw) {
                unsigned long long xp0 = pack2(xr[kh + 0][kw], xr[kh + 0][kw + 1]);
                unsigned long long xp1 = pack2(xr[kh + 1][kw], xr[kh + 1][kw + 1]);
                const int k = kh * 3 + kw;
#pragma unroll
                for (int ol = 0; ol < 16; ++ol) {
                    float wv = wsm[ol * 9 + k];
                    unsigned long long wp = pack2(wv, wv);
                    acc[ol][0] = ffma2(xp0, wp, acc[ol][0]);
                    acc[ol][1] = ffma2(xp1, wp, acc[ol][1]);
                }
            }
        }
        __syncthreads();
    }

    // epilogue: add fused bias, coalesced float2 stores
    const int ybase = sy * 32 + 2 * ty;
    const int xbase = sx * 32 + 2 * tx;
#pragma unroll
    for (int ol = 0; ol < 16; ++ol) {
        float bv = g_beff[og * 16 + ol];
        size_t obase = (((size_t)n * C_OUT + og * 16 + ol) * HH + ybase) * WW + xbase;
#pragma unroll
        for (int py = 0; py < 2; ++py) {
            float lo, hi;
            unpack2(acc[ol][py], lo, hi);
            float2 v = make_float2(lo + bv, hi + bv);
            *reinterpret_cast<float2*>(out + obase + (size_t)py * WW) = v;
        }
    }
}

// ---------------------------------------------------------------------------
extern "C" void kernel_launch(void* const* d_in, const int* in_sizes, int n_in,
                              void* d_out, int out_size) {
    const float* x  = (const float*)d_in[0];
    const float* w  = (const float*)d_in[1];
    const float* b  = (const float*)d_in[2];
    const float* wc = (const float*)d_in[3];
    const float* bc = (const float*)d_in[4];
    const float* gt = (const float*)d_in[5];
    float* out = (float*)d_out;

    scale_kernel<<<2, 256>>>(w, wc);
    prep_kernel<<<(W_ELEMS + 255) / 256, 256>>>(w, b, wc, bc, gt);
    dim3 grid(4, 16, N_IMG);
    conv_kernel<<<grid, 256>>>(x, out);
}

// round 4
// speedup vs baseline: 10.5554x; 10.5554x over previous
#include <cuda_runtime.h>
#include <cuda_fp16.h>
#include <cstdint>

// ---------------------------------------------------------------------------
// Problem constants
// ---------------------------------------------------------------------------
#define N_IMG   16
#define C_IN    64
#define C_OUT   64
#define HH      128
#define WW      128
#define W_ELEMS (C_OUT * C_IN * 9)      // 36864
#define HP      130                      // padded H/W
#define XP_ELEMS (N_IMG * HP * HP * 64)  // fp16 padded NHWC scratch

// ---------------------------------------------------------------------------
// Persistent device scratch (zero-initialized; g_xp borders stay 0 forever)
// ---------------------------------------------------------------------------
__device__ double  g_part[32];
__device__ float   g_scale[2];
__device__ __half  g_xp[XP_ELEMS];        // [n][h+1][w+1][c]
__device__ __half  g_wB[9 * 64 * 64];     // [tap][oc][c]
__device__ float   g_beff[C_OUT];

// ---------------------------------------------------------------------------
// PTX helpers (sm_103-baseline only: cp.async, ldmatrix, mma.sync)
// ---------------------------------------------------------------------------
__device__ __forceinline__ uint32_t smem_to_u32(const void* p) {
    uint32_t a;
    asm("{ .reg .u64 t; cvta.to.shared.u64 t, %1; cvt.u32.u64 %0, t; }"
        : "=r"(a) : "l"(p));
    return a;
}
__device__ __forceinline__ void cp16(uint32_t dst, const void* src) {
    asm volatile("cp.async.cg.shared.global [%0], [%1], 16;" :: "r"(dst), "l"(src));
}
__device__ __forceinline__ void cp_commit() {
    asm volatile("cp.async.commit_group;" ::: "memory");
}
__device__ __forceinline__ void cp_wait_all() {
    asm volatile("cp.async.wait_all;" ::: "memory");
}
__device__ __forceinline__ void cp_wait1() {
    asm volatile("cp.async.wait_group 1;" ::: "memory");
}
__device__ __forceinline__ void cp_wait0() {
    asm volatile("cp.async.wait_group 0;" ::: "memory");
}
__device__ __forceinline__ void ldsm_x4(uint32_t* r, uint32_t addr) {
    asm volatile("ldmatrix.sync.aligned.m8n8.x4.shared.b16 {%0,%1,%2,%3}, [%4];"
        : "=r"(r[0]), "=r"(r[1]), "=r"(r[2]), "=r"(r[3]) : "r"(addr));
}
__device__ __forceinline__ void mma16816(float* d, const uint32_t* a, const uint32_t* b) {
    asm volatile(
        "mma.sync.aligned.m16n8k16.row.col.f32.f16.f16.f32 "
        "{%0,%1,%2,%3}, {%4,%5,%6,%7}, {%8,%9}, {%0,%1,%2,%3};"
        : "+f"(d[0]), "+f"(d[1]), "+f"(d[2]), "+f"(d[3])
        : "r"(a[0]), "r"(a[1]), "r"(a[2]), "r"(a[3]), "r"(b[0]), "r"(b[1]));
}

// ---------------------------------------------------------------------------
// Kernel 1a/1b: per-tensor scale = max(mean(|w|), 1e-5), fp64, deterministic
// ---------------------------------------------------------------------------
__global__ void scale_part_kernel(const float* __restrict__ w,
                                  const float* __restrict__ wc) {
    int b = blockIdx.x;                  // 0..31
    const float* p = (b < 16) ? w : wc;
    int seg = b & 15;
    int start = seg * (W_ELEMS / 16);
    double s = 0.0;
    for (int i = start + threadIdx.x; i < start + W_ELEMS / 16; i += 256)
        s += (double)fabsf(p[i]);
    __shared__ double red[256];
    red[threadIdx.x] = s;
    __syncthreads();
    for (int off = 128; off > 0; off >>= 1) {
        if (threadIdx.x < off) red[threadIdx.x] += red[threadIdx.x + off];
        __syncthreads();
    }
    if (threadIdx.x == 0) g_part[b] = red[0];
}
__global__ void scale_final_kernel() {
    int t = threadIdx.x;
    if (t < 2) {
        double s = 0.0;
        for (int i = 0; i < 16; ++i) s += g_part[t * 16 + i];
        g_scale[t] = fmaxf((float)(s / (double)W_ELEMS), 1e-5f);
    }
}

// ---------------------------------------------------------------------------
// Kernel 2: fuse ternary-quantized weights -> fp16 [tap][oc][c]; fuse bias
// ---------------------------------------------------------------------------
__global__ void prep_kernel(const float* __restrict__ w,
                            const float* __restrict__ b,
                            const float* __restrict__ wc,
                            const float* __restrict__ bc,
                            const float* __restrict__ gate) {
    int i = blockIdx.x * 256 + threadIdx.x;
    float g = 1.0f / (1.0f + expf(-gate[0]));
    if (i < W_ELEMS) {
        float s1 = g_scale[0], s2 = g_scale[1];
        float q1 = fminf(fmaxf(rintf(w[i]  / s1), -1.0f), 1.0f) * s1;
        float q2 = fminf(fmaxf(rintf(wc[i] / s2), -1.0f), 1.0f) * s2;
        int o = i / (C_IN * 9);
        int r = i - o * (C_IN * 9);
        int c = r / 9;
        int k = r - c * 9;
        g_wB[k * 4096 + o * 64 + c] = __float2half_rn(q1 + g * q2);
    }
    if (i < C_OUT)
        g_beff[i] = b[i] + g * bc[i];
}

// ---------------------------------------------------------------------------
// Kernel 3: NCHW fp32 -> padded NHWC fp16 transpose
// ---------------------------------------------------------------------------
__global__ __launch_bounds__(256)
void transpose_kernel(const float* __restrict__ x) {
    const int w0 = blockIdx.x * 32;
    const int h  = blockIdx.y;
    const int n  = blockIdx.z;
    const int tid = threadIdx.x;

    __shared__ float s[32 * 65];
#pragma unroll
    for (int i = 0; i < 8; ++i) {
        int idx = tid + i * 256;
        int c = idx >> 5, wc = idx & 31;
        s[wc * 65 + c] = x[(((size_t)n * 64 + c) * HH + h) * WW + w0 + wc];
    }
    __syncthreads();

    int wc = tid >> 3;
    int cg = (tid & 7) * 8;
    alignas(16) __half h8[8];
#pragma unroll
    for (int j = 0; j < 8; ++j)
        h8[j] = __float2half_rn(s[wc * 65 + cg + j]);
    size_t dst = (((size_t)n * HP + (h + 1)) * HP + (w0 + wc + 1)) * 64 + cg;
    *reinterpret_cast<uint4*>(&g_xp[dst]) = *reinterpret_cast<const uint4*>(h8);
}

// ---------------------------------------------------------------------------
// Kernel 4: persistent implicit-GEMM conv via HMMA (mma.sync m16n8k16)
//   tile = one output row: M=128 pixels, N=64 oc, K=9 taps x 64 ch
// SMEM layout (byte offsets, all multiples of 128):
//   B:    [0, 73728)           9 taps x 64oc x 128B rows (XOR-swizzled)
//   A:    [73728, 173568)      2 bufs x 3 rows x 130 px x 128B (swizzled)
//   OUT:  [173568, 207360)     64 x 132 fp32 transpose buffer
//   BIAS: [207360, 207616)
// ---------------------------------------------------------------------------
#define AROW_B   16640              // 130*128
#define ABUF_B   (3 * AROW_B)       // 49920
#define A_OFF    73728
#define OUT_OFF  173568
#define BIAS_OFF 207360
#define SMEM_CONV 207872
#define NTILES   (N_IMG * HH)       // 2048

__device__ __forceinline__ void stage_A(uint32_t abuf, int t, int tid) {
    const int n = t >> 7, y = t & 127;
    const char* src = reinterpret_cast<const char*>(
        g_xp + ((size_t)n * HP + y) * HP * 64);
    for (int i = tid; i < 3120; i += 256) {       // 3 rows x 1040 16B-chunks
        int r = i / 1040;
        int k = i - r * 1040;
        int p = k >> 3, j = k & 7;
        cp16(abuf + r * AROW_B + p * 128 + ((j ^ (p & 7)) << 4),
             src + (size_t)r * AROW_B + (size_t)k * 16);
    }
}

__global__ __launch_bounds__(256, 1)
void conv_kernel(float* __restrict__ out) {
    extern __shared__ char sm[];
    const uint32_t base = smem_to_u32(sm);
    const int tid  = threadIdx.x;
    const int wid  = tid >> 5;
    const int lane = tid & 31;

    float* out_sm  = reinterpret_cast<float*>(sm + OUT_OFF);
    float* bias_sm = reinterpret_cast<float*>(sm + BIAS_OFF);
    if (tid < 64) bias_sm[tid] = g_beff[tid];

    // Stage all 9 weight tiles (swizzled: chunk j of oc-row nr -> j^(nr&7))
    for (int k = tid; k < 4608; k += 256) {
        int q = k & 511;
        int nr = q >> 3, j = q & 7;
        cp16(base + (k >> 9) * 8192 + nr * 128 + ((j ^ (nr & 7)) << 4),
             reinterpret_cast<const char*>(g_wB) + (size_t)k * 16);
    }
    cp_commit();

    const int t0 = blockIdx.x;
    if (t0 < NTILES) stage_A(base + A_OFF, t0, tid);
    cp_commit();
    cp_wait_all();
    __syncthreads();

    const int m0 = (wid >> 1) * 32;          // warp pixel base
    const int n0 = (wid & 1) * 32;           // warp oc base
    const int a_pl = lane & 15, a_hk = lane >> 4;
    const int b_nl = (lane & 7) + ((lane >> 4) << 3);
    const int b_hk = (lane >> 3) & 1;

    int buf = 0;
    for (int t = t0; t < NTILES; t += gridDim.x) {
        const int nxt = t + gridDim.x;
        if (nxt < NTILES) {
            stage_A(base + A_OFF + (buf ^ 1) * ABUF_B, nxt, tid);
            cp_commit();
        }
        if (t != t0) {                        // first tile already waited
            if (nxt < NTILES) cp_wait1(); else cp_wait0();
            __syncthreads();
        }

        float acc[2][4][4];
#pragma unroll
        for (int mi = 0; mi < 2; ++mi)
#pragma unroll
            for (int nj = 0; nj < 4; ++nj)
#pragma unroll
                for (int r = 0; r < 4; ++r) acc[mi][nj][r] = 0.0f;

        const uint32_t abase = base + A_OFF + buf * ABUF_B;
#pragma unroll 1
        for (int dy = 0; dy < 3; ++dy) {
            const uint32_t arow = abase + dy * AROW_B;
#pragma unroll
            for (int dx = 0; dx < 3; ++dx) {
                const uint32_t btap = base + (dy * 3 + dx) * 8192;
#pragma unroll
                for (int kc = 0; kc < 4; ++kc) {
                    uint32_t a[2][4];
#pragma unroll
                    for (int mi = 0; mi < 2; ++mi) {
                        int pix = m0 + mi * 16 + a_pl + dx;
                        uint32_t addr = arow + pix * 128 +
                            (((2 * kc + a_hk) ^ (pix & 7)) << 4);
                        ldsm_x4(a[mi], addr);
                    }
#pragma unroll
                    for (int nj = 0; nj < 2; ++nj) {
                        uint32_t b[4];
                        int nn = n0 + nj * 16 + b_nl;
                        uint32_t addr = btap + nn * 128 +
                            (((2 * kc + b_hk) ^ (b_nl & 7)) << 4);
                        ldsm_x4(b, addr);
#pragma unroll
                        for (int mi = 0; mi < 2; ++mi) {
                            mma16816(acc[mi][nj * 2 + 0], a[mi], b + 0);
                            mma16816(acc[mi][nj * 2 + 1], a[mi], b + 2);
                        }
                    }
                }
            }
        }

        // acc -> SMEM transpose (pitch 132 floats kills bank conflicts)
        {
            int r  = lane >> 2;
            int c2 = (lane & 3) * 2;
#pragma unroll
            for (int mi = 0; mi < 2; ++mi) {
                int p = m0 + mi * 16 + r;
#pragma unroll
                for (int nj = 0; nj < 4; ++nj) {
                    int oc = n0 + nj * 8 + c2;
                    out_sm[oc * 132 + p]           = acc[mi][nj][0];
                    out_sm[(oc + 1) * 132 + p]     = acc[mi][nj][1];
                    out_sm[oc * 132 + p + 8]       = acc[mi][nj][2];
                    out_sm[(oc + 1) * 132 + p + 8] = acc[mi][nj][3];
                }
            }
        }
        __syncthreads();

        // Coalesced float4 stores with fused bias
        {
            const int n = t >> 7, y = t & 127;
            float* ob = out + (size_t)n * (64 * 16384) + (size_t)y * 128;
#pragma unroll
            for (int i = tid; i < 2048; i += 256) {
                int row = i >> 5, c4 = (i & 31) * 4;
                float4 v = *reinterpret_cast<float4*>(&out_sm[row * 132 + c4]);
                float bv = bias_sm[row];
                v.x += bv; v.y += bv; v.z += bv; v.w += bv;
                *reinterpret_cast<float4*>(&ob[(size_t)row * 16384 + c4]) = v;
            }
        }
        __syncthreads();   // out_sm free for next tile
        buf ^= 1;
    }
}

// ---------------------------------------------------------------------------
extern "C" void kernel_launch(void* const* d_in, const int* in_sizes, int n_in,
                              void* d_out, int out_size) {
    const float* x  = (const float*)d_in[0];
    const float* w  = (const float*)d_in[1];
    const float* b  = (const float*)d_in[2];
    const float* wc = (const float*)d_in[3];
    const float* bc = (const float*)d_in[4];
    const float* gt = (const float*)d_in[5];
    float* out = (float*)d_out;

    cudaFuncSetAttribute(conv_kernel,
                         cudaFuncAttributeMaxDynamicSharedMemorySize, SMEM_CONV);

    scale_part_kernel<<<32, 256>>>(w, wc);
    scale_final_kernel<<<1, 32>>>();
    prep_kernel<<<(W_ELEMS + 255) / 256, 256>>>(w, b, wc, bc, gt);
    transpose_kernel<<<dim3(4, HH, N_IMG), 256>>>(x);
    conv_kernel<<<148, 256, SMEM_CONV>>>(out);
}

// round 5
// speedup vs baseline: 11.9415x; 1.1313x over previous
#include <cuda_runtime.h>
#include <cuda_fp16.h>
#include <cstdint>

// ---------------------------------------------------------------------------
// Problem constants
// ---------------------------------------------------------------------------
#define N_IMG   16
#define C_IN    64
#define C_OUT   64
#define HH      128
#define WW      128
#define W_ELEMS (C_OUT * C_IN * 9)      // 36864
#define HP      130                      // padded H/W
#define XP_ELEMS (N_IMG * HP * HP * 64)  // fp16 padded NHWC scratch

// ---------------------------------------------------------------------------
// Persistent device scratch (zero-initialized; g_xp borders stay 0 forever)
// ---------------------------------------------------------------------------
__device__ double  g_part[32];
__device__ __half  g_xp[XP_ELEMS];        // [n][h+1][w+1][c]
__device__ __half  g_wB[9 * 64 * 64];     // [tap][oc][c]
__device__ float   g_beff[C_OUT];

// ---------------------------------------------------------------------------
// PTX helpers (sm_103-baseline: cp.async, ldmatrix, mma.sync)
// ---------------------------------------------------------------------------
__device__ __forceinline__ uint32_t smem_to_u32(const void* p) {
    uint32_t a;
    asm("{ .reg .u64 t; cvta.to.shared.u64 t, %1; cvt.u32.u64 %0, t; }"
        : "=r"(a) : "l"(p));
    return a;
}
__device__ __forceinline__ void cp16(uint32_t dst, const void* src) {
    asm volatile("cp.async.cg.shared.global [%0], [%1], 16;" :: "r"(dst), "l"(src));
}
__device__ __forceinline__ void cp_commit() {
    asm volatile("cp.async.commit_group;" ::: "memory");
}
__device__ __forceinline__ void cp_wait0() {
    asm volatile("cp.async.wait_group 0;" ::: "memory");
}
__device__ __forceinline__ void cp_wait1() {
    asm volatile("cp.async.wait_group 1;" ::: "memory");
}
__device__ __forceinline__ void ldsm_x4(uint32_t* r, uint32_t addr) {
    asm volatile("ldmatrix.sync.aligned.m8n8.x4.shared.b16 {%0,%1,%2,%3}, [%4];"
        : "=r"(r[0]), "=r"(r[1]), "=r"(r[2]), "=r"(r[3]) : "r"(addr));
}
__device__ __forceinline__ void mma16816(float* d, const uint32_t* a, const uint32_t* b) {
    asm volatile(
        "mma.sync.aligned.m16n8k16.row.col.f32.f16.f16.f32 "
        "{%0,%1,%2,%3}, {%4,%5,%6,%7}, {%8,%9}, {%0,%1,%2,%3};"
        : "+f"(d[0]), "+f"(d[1]), "+f"(d[2]), "+f"(d[3])
        : "r"(a[0]), "r"(a[1]), "r"(a[2]), "r"(a[3]), "r"(b[0]), "r"(b[1]));
}

// ---------------------------------------------------------------------------
// Kernel 1: partial |w| sums (fp64, deterministic)
// ---------------------------------------------------------------------------
__global__ void scale_part_kernel(const float* __restrict__ w,
                                  const float* __restrict__ wc) {
    int b = blockIdx.x;                  // 0..31
    const float* p = (b < 16) ? w : wc;
    int seg = b & 15;
    int start = seg * (W_ELEMS / 16);
    double s = 0.0;
    for (int i = start + threadIdx.x; i < start + W_ELEMS / 16; i += 256)
        s += (double)fabsf(p[i]);
    __shared__ double red[256];
    red[threadIdx.x] = s;
    __syncthreads();
    for (int off = 128; off > 0; off >>= 1) {
        if (threadIdx.x < off) red[threadIdx.x] += red[threadIdx.x + off];
        __syncthreads();
    }
    if (threadIdx.x == 0) g_part[b] = red[0];
}

// ---------------------------------------------------------------------------
// Kernel 2: finalize scales (redundant per block) + fuse ternary weights
//           -> fp16 [tap][oc][c]; fuse bias
// ---------------------------------------------------------------------------
__global__ void prep_kernel(const float* __restrict__ w,
                            const float* __restrict__ b,
                            const float* __restrict__ wc,
                            const float* __restrict__ bc,
                            const float* __restrict__ gate) {
    __shared__ float ssc[2];
    if (threadIdx.x < 2) {
        double s = 0.0;
        for (int i = 0; i < 16; ++i) s += g_part[threadIdx.x * 16 + i];
        ssc[threadIdx.x] = fmaxf((float)(s / (double)W_ELEMS), 1e-5f);
    }
    __syncthreads();
    int i = blockIdx.x * 256 + threadIdx.x;
    float g = 1.0f / (1.0f + expf(-gate[0]));
    if (i < W_ELEMS) {
        float s1 = ssc[0], s2 = ssc[1];
        float q1 = fminf(fmaxf(rintf(w[i]  / s1), -1.0f), 1.0f) * s1;
        float q2 = fminf(fmaxf(rintf(wc[i] / s2), -1.0f), 1.0f) * s2;
        int o = i / (C_IN * 9);
        int r = i - o * (C_IN * 9);
        int c = r / 9;
        int k = r - c * 9;
        g_wB[k * 4096 + o * 64 + c] = __float2half_rn(q1 + g * q2);
    }
    if (i < C_OUT)
        g_beff[i] = b[i] + g * bc[i];
}

// ---------------------------------------------------------------------------
// Kernel 3: NCHW fp32 -> padded NHWC fp16 transpose (float4 loads)
// ---------------------------------------------------------------------------
__global__ __launch_bounds__(256)
void transpose_kernel(const float* __restrict__ x) {
    const int w0 = blockIdx.x * 32;
    const int h  = blockIdx.y;
    const int n  = blockIdx.z;
    const int tid = threadIdx.x;

    __shared__ float s[32 * 65];
#pragma unroll
    for (int it = 0; it < 2; ++it) {
        int i = tid + it * 256;            // 0..511
        int c = i >> 3, j = i & 7;
        float4 v = *reinterpret_cast<const float4*>(
            x + (((size_t)(n * 64 + c)) * HH + h) * WW + w0 + j * 4);
        int wb = j * 4;
        s[(wb + 0) * 65 + c] = v.x;
        s[(wb + 1) * 65 + c] = v.y;
        s[(wb + 2) * 65 + c] = v.z;
        s[(wb + 3) * 65 + c] = v.w;
    }
    __syncthreads();

    int wc = tid >> 3;
    int cg = (tid & 7) * 8;
    alignas(16) __half h8[8];
#pragma unroll
    for (int j = 0; j < 8; ++j)
        h8[j] = __float2half_rn(s[wc * 65 + cg + j]);
    size_t dst = (((size_t)n * HP + (h + 1)) * HP + (w0 + wc + 1)) * 64 + cg;
    *reinterpret_cast<uint4*>(&g_xp[dst]) = *reinterpret_cast<const uint4*>(h8);
}

// ---------------------------------------------------------------------------
// Kernel 4: persistent implicit-GEMM conv via HMMA (mma.sync m16n8k16)
//   tile = TWO output rows: M=256 pixels, N=64 oc, K=9 taps x 64 ch
//   4 staged input rows serve both output rows (rolling-pair reuse)
// SMEM:
//   B:  [0, 73728)            9 taps x 64oc x 128B (XOR-swizzled)
//   A:  [73728, 206848)       2 bufs x 4 rows x 130px x 128B (swizzled)
// ---------------------------------------------------------------------------
#define AROW_B   16640              // 130*128
#define ABUF_B   (4 * AROW_B)       // 66560
#define A_OFF    73728
#define SMEM_CONV 206848
#define NTILES2  1024               // 16 images * 64 row-pairs

__device__ __forceinline__ void stage_A(uint32_t abuf, int t, int tid) {
    const int n = t >> 6, y0 = (t & 63) * 2;
    const char* src = reinterpret_cast<const char*>(
        g_xp + ((size_t)n * HP + y0) * HP * 64);
    for (int i = tid; i < 4160; i += 256) {       // 4 rows x 1040 16B-chunks
        int r = i / 1040;
        int k = i - r * 1040;
        int p = k >> 3, j = k & 7;
        cp16(abuf + r * AROW_B + p * 128 + ((j ^ (p & 7)) << 4),
             src + (size_t)r * AROW_B + (size_t)k * 16);
    }
}

__global__ __launch_bounds__(256, 1)
void conv_kernel(float* __restrict__ out) {
    extern __shared__ char sm[];
    const uint32_t base = smem_to_u32(sm);
    const int tid  = threadIdx.x;
    const int wid  = tid >> 5;
    const int lane = tid & 31;

    // Stage all 9 weight tiles (swizzle: chunk j of oc-row nr -> j^(nr&7))
    for (int k = tid; k < 4608; k += 256) {
        int q = k & 511;
        int nr = q >> 3, j = q & 7;
        cp16(base + (k >> 9) * 8192 + nr * 128 + ((j ^ (nr & 7)) << 4),
             reinterpret_cast<const char*>(g_wB) + (size_t)k * 16);
    }
    cp_commit();

    const int t0 = blockIdx.x;
    if (t0 < NTILES2) stage_A(base + A_OFF, t0, tid);
    cp_commit();
    cp_wait0();
    __syncthreads();

    // Warp layout: rw = output row within pair, m0 = 32-pixel quadrant
    const int rw = wid >> 2;
    const int m0 = (wid & 3) * 32;
    const int a_pl = lane & 15, a_hk = lane >> 4;
    const int b_nl = (lane & 7) + ((lane >> 4) << 3);
    const int b_hk = (lane >> 3) & 1;

    // Per-thread bias registers: oc = nj*8 + (lane&3)*2 + {0,1}
    float bv[8][2];
#pragma unroll
    for (int nj = 0; nj < 8; ++nj) {
        bv[nj][0] = g_beff[nj * 8 + (lane & 3) * 2];
        bv[nj][1] = g_beff[nj * 8 + (lane & 3) * 2 + 1];
    }

    int buf = 0;
    for (int t = t0; t < NTILES2; t += gridDim.x) {
        const int nxt = t + gridDim.x;
        if (nxt < NTILES2) {
            stage_A(base + A_OFF + (buf ^ 1) * ABUF_B, nxt, tid);
            cp_commit();
        }
        if (t != t0) {
            if (nxt < NTILES2) cp_wait1(); else cp_wait0();
            __syncthreads();
        }

        float acc[2][8][4];
#pragma unroll
        for (int mi = 0; mi < 2; ++mi)
#pragma unroll
            for (int nj = 0; nj < 8; ++nj)
#pragma unroll
                for (int r = 0; r < 4; ++r) acc[mi][nj][r] = 0.0f;

        const uint32_t abase = base + A_OFF + buf * ABUF_B;
#pragma unroll 1
        for (int dy = 0; dy < 3; ++dy) {
            const uint32_t arow = abase + (rw + dy) * AROW_B;
#pragma unroll
            for (int dx = 0; dx < 3; ++dx) {
                const uint32_t btap = base + (dy * 3 + dx) * 8192;
#pragma unroll
                for (int kc = 0; kc < 4; ++kc) {
                    uint32_t a[2][4];
#pragma unroll
                    for (int mi = 0; mi < 2; ++mi) {
                        int pix = m0 + mi * 16 + a_pl + dx;
                        ldsm_x4(a[mi], arow + pix * 128 +
                                (((2 * kc + a_hk) ^ (pix & 7)) << 4));
                    }
#pragma unroll
                    for (int nj = 0; nj < 4; ++nj) {
                        uint32_t b[4];
                        int nn = nj * 16 + b_nl;
                        ldsm_x4(b, btap + nn * 128 +
                                (((2 * kc + b_hk) ^ (b_nl & 7)) << 4));
#pragma unroll
                        for (int mi = 0; mi < 2; ++mi) {
                            mma16816(acc[mi][nj * 2 + 0], a[mi], b + 0);
                            mma16816(acc[mi][nj * 2 + 1], a[mi], b + 2);
                        }
                    }
                }
            }
        }

        // Direct epilogue: STG.32 from fragments, bias fused in registers
        {
            const int n = t >> 6, y = (t & 63) * 2 + rw;
            float* ob = out + (size_t)n * (64 * 16384) + (size_t)y * 128;
            const int pl = lane >> 2;
#pragma unroll
            for (int mi = 0; mi < 2; ++mi) {
                int pbase = m0 + mi * 16 + pl;
#pragma unroll
                for (int nj = 0; nj < 8; ++nj) {
                    float* p0 = ob + (size_t)(nj * 8 + (lane & 3) * 2) * 16384;
                    p0[pbase]             = acc[mi][nj][0] + bv[nj][0];
                    p0[16384 + pbase]     = acc[mi][nj][1] + bv[nj][1];
                    p0[pbase + 8]         = acc[mi][nj][2] + bv[nj][0];
                    p0[16384 + pbase + 8] = acc[mi][nj][3] + bv[nj][1];
                }
            }
        }
        __syncthreads();   // all warps done reading buf before it is restaged
        buf ^= 1;
    }
}

// ---------------------------------------------------------------------------
extern "C" void kernel_launch(void* const* d_in, const int* in_sizes, int n_in,
                              void* d_out, int out_size) {
    const float* x  = (const float*)d_in[0];
    const float* w  = (const float*)d_in[1];
    const float* b  = (const float*)d_in[2];
    const float* wc = (const float*)d_in[3];
    const float* bc = (const float*)d_in[4];
    const float* gt = (const float*)d_in[5];
    float* out = (float*)d_out;

    static bool attr_set = false;
    if (!attr_set) {
        cudaFuncSetAttribute(conv_kernel,
                             cudaFuncAttributeMaxDynamicSharedMemorySize, SMEM_CONV);
        attr_set = true;
    }

    scale_part_kernel<<<32, 256>>>(w, wc);
    prep_kernel<<<(W_ELEMS + 255) / 256, 256>>>(w, b, wc, bc, gt);
    transpose_kernel<<<dim3(4, HH, N_IMG), 256>>>(x);
    conv_kernel<<<148, 256, SMEM_CONV>>>(out);
}